// round 1
// baseline (speedup 1.0000x reference)
#include <cuda_runtime.h>
#include <math.h>
#include <stdint.h>

// Problem dims (fixed by the dataset)
#define BATCH 4
#define SEQ   4096
#define DIM   1024
#define NTOK  (BATCH * SEQ)   // 16384

// GEMM tiling
#define BM 128
#define BN 128
#define BK 16

// Scratch in device globals (no cudaMalloc allowed)
__device__ float g_q[(size_t)NTOK * DIM];
__device__ float g_k[(size_t)NTOK * DIM];
__device__ float g_v[(size_t)NTOK * DIM];
__device__ float g_ctx[(size_t)NTOK * DIM];
__device__ float g_p[(size_t)BATCH * SEQ * SEQ];

// ---------------------------------------------------------------------------
// Generic NN GEMM: C = A @ B (+ bias), 128x128x16 tile, 256 threads,
// 8x8 per thread split into 4-wide segments at tx*4 and tx*4+64 (conflict-free LDS).
// causal_klimit: when 1, K loop stops at (bm+1)*BM (used for P@V — upper-tri P is 0).
// Batched via blockIdx.z with element strides sA/sB/sC.
// ---------------------------------------------------------------------------
__global__ __launch_bounds__(256) void gemm_nn(
    const float* __restrict__ A, const float* __restrict__ Bm,
    const float* __restrict__ bias, float* __restrict__ C,
    int M, int N, int K, int causal_klimit,
    size_t sA, size_t sB, size_t sC)
{
    __shared__ __align__(16) float As[BK][BM];
    __shared__ __align__(16) float Bs[BK][BN];

    const int bm = blockIdx.y, bn = blockIdx.x, bz = blockIdx.z;
    const int tid = threadIdx.x;
    const int tx = tid & 15, ty = tid >> 4;

    int Kend = K;
    if (causal_klimit) { int lim = (bm + 1) * BM; if (lim < Kend) Kend = lim; }

    const int a_row = tid >> 2;          // 0..63 (plus +64)
    const int a_col = (tid & 3) << 2;    // 0,4,8,12
    const int b_row = tid >> 5;          // 0..7 (plus +8)
    const int b_col = (tid & 31) << 2;   // 0..124

    const float* Ab = A + (size_t)bz * sA + (size_t)bm * BM * K;
    const float* Bb = Bm + (size_t)bz * sB + bn * BN;
    float*       Cb = C + (size_t)bz * sC;

    float acc[8][8];
#pragma unroll
    for (int i = 0; i < 8; i++)
#pragma unroll
        for (int j = 0; j < 8; j++) acc[i][j] = 0.f;

    for (int k0 = 0; k0 < Kend; k0 += BK) {
#pragma unroll
        for (int i = 0; i < 2; i++) {
            int r = a_row + i * 64;
            float4 v = *(const float4*)(Ab + (size_t)r * K + (k0 + a_col));
            As[a_col + 0][r] = v.x;
            As[a_col + 1][r] = v.y;
            As[a_col + 2][r] = v.z;
            As[a_col + 3][r] = v.w;
        }
#pragma unroll
        for (int i = 0; i < 2; i++) {
            int r = b_row + i * 8;
            float4 v = *(const float4*)(Bb + (size_t)(k0 + r) * N + b_col);
            *(float4*)&Bs[r][b_col] = v;
        }
        __syncthreads();
#pragma unroll
        for (int k = 0; k < BK; k++) {
            float4 a0 = *(const float4*)&As[k][ty * 4];
            float4 a1 = *(const float4*)&As[k][ty * 4 + 64];
            float4 b0 = *(const float4*)&Bs[k][tx * 4];
            float4 b1 = *(const float4*)&Bs[k][tx * 4 + 64];
            float a[8] = {a0.x, a0.y, a0.z, a0.w, a1.x, a1.y, a1.z, a1.w};
            float b[8] = {b0.x, b0.y, b0.z, b0.w, b1.x, b1.y, b1.z, b1.w};
#pragma unroll
            for (int i = 0; i < 8; i++)
#pragma unroll
                for (int j = 0; j < 8; j++)
                    acc[i][j] += a[i] * b[j];
        }
        __syncthreads();
    }

#pragma unroll
    for (int ii = 0; ii < 2; ii++)
#pragma unroll
        for (int i = 0; i < 4; i++) {
            int row = bm * BM + ty * 4 + ii * 64 + i;
#pragma unroll
            for (int jj = 0; jj < 2; jj++) {
                int col = bn * BN + tx * 4 + jj * 64;
                float4 v;
                v.x = acc[ii * 4 + i][jj * 4 + 0];
                v.y = acc[ii * 4 + i][jj * 4 + 1];
                v.z = acc[ii * 4 + i][jj * 4 + 2];
                v.w = acc[ii * 4 + i][jj * 4 + 3];
                if (bias) {
                    float4 bb = *(const float4*)(bias + col);
                    v.x += bb.x; v.y += bb.y; v.z += bb.z; v.w += bb.w;
                }
                *(float4*)(Cb + (size_t)row * N + col) = v;
            }
        }
}

// ---------------------------------------------------------------------------
// NT GEMM for scores: P[m,n] = scale * sum_k Q[m,k]*K[n,k].
// Skips tiles strictly above the diagonal (bn > bm). Diagonal tiles write
// garbage above the diagonal; softmax never reads those entries.
// ---------------------------------------------------------------------------
__global__ __launch_bounds__(256) void gemm_nt_scores(
    const float* __restrict__ Q, const float* __restrict__ Km,
    float* __restrict__ P, float scale)
{
    const int bm = blockIdx.y, bn = blockIdx.x, bz = blockIdx.z;
    if (bn > bm) return;

    __shared__ __align__(16) float As[BK][BM];
    __shared__ __align__(16) float Bs[BK][BN];

    const int tid = threadIdx.x;
    const int tx = tid & 15, ty = tid >> 4;

    const int a_row = tid >> 2;
    const int a_col = (tid & 3) << 2;

    const float* Qb = Q + ((size_t)bz * SEQ + (size_t)bm * BM) * DIM;
    const float* Kb = Km + ((size_t)bz * SEQ + (size_t)bn * BN) * DIM;
    float*       Pb = P + (size_t)bz * SEQ * SEQ;

    float acc[8][8];
#pragma unroll
    for (int i = 0; i < 8; i++)
#pragma unroll
        for (int j = 0; j < 8; j++) acc[i][j] = 0.f;

    for (int k0 = 0; k0 < DIM; k0 += BK) {
#pragma unroll
        for (int i = 0; i < 2; i++) {
            int r = a_row + i * 64;
            float4 v = *(const float4*)(Qb + (size_t)r * DIM + (k0 + a_col));
            As[a_col + 0][r] = v.x;
            As[a_col + 1][r] = v.y;
            As[a_col + 2][r] = v.z;
            As[a_col + 3][r] = v.w;
        }
#pragma unroll
        for (int i = 0; i < 2; i++) {
            int r = a_row + i * 64;
            float4 v = *(const float4*)(Kb + (size_t)r * DIM + (k0 + a_col));
            Bs[a_col + 0][r] = v.x;
            Bs[a_col + 1][r] = v.y;
            Bs[a_col + 2][r] = v.z;
            Bs[a_col + 3][r] = v.w;
        }
        __syncthreads();
#pragma unroll
        for (int k = 0; k < BK; k++) {
            float4 a0 = *(const float4*)&As[k][ty * 4];
            float4 a1 = *(const float4*)&As[k][ty * 4 + 64];
            float4 b0 = *(const float4*)&Bs[k][tx * 4];
            float4 b1 = *(const float4*)&Bs[k][tx * 4 + 64];
            float a[8] = {a0.x, a0.y, a0.z, a0.w, a1.x, a1.y, a1.z, a1.w};
            float b[8] = {b0.x, b0.y, b0.z, b0.w, b1.x, b1.y, b1.z, b1.w};
#pragma unroll
            for (int i = 0; i < 8; i++)
#pragma unroll
                for (int j = 0; j < 8; j++)
                    acc[i][j] += a[i] * b[j];
        }
        __syncthreads();
    }

#pragma unroll
    for (int ii = 0; ii < 2; ii++)
#pragma unroll
        for (int i = 0; i < 4; i++) {
            int row = bm * BM + ty * 4 + ii * 64 + i;
#pragma unroll
            for (int jj = 0; jj < 2; jj++) {
                int col = bn * BN + tx * 4 + jj * 64;
                float4 v;
                v.x = acc[ii * 4 + i][jj * 4 + 0] * scale;
                v.y = acc[ii * 4 + i][jj * 4 + 1] * scale;
                v.z = acc[ii * 4 + i][jj * 4 + 2] * scale;
                v.w = acc[ii * 4 + i][jj * 4 + 3] * scale;
                *(float4*)(Pb + (size_t)row * SEQ + col) = v;
            }
        }
}

// ---------------------------------------------------------------------------
// Causal row softmax: one 256-thread block per row. Reads only j <= row,
// writes the full row (zeros beyond the diagonal so P@V needs no masking).
// ---------------------------------------------------------------------------
__global__ __launch_bounds__(256) void softmax_causal(float* __restrict__ P)
{
    __shared__ float red[33];
    const int row = blockIdx.x;
    const int bz  = blockIdx.y;
    float* p = P + ((size_t)bz * SEQ + row) * SEQ;
    const int n = row + 1;
    const int t = threadIdx.x;

    float vals[16];
    float mx = -INFINITY;
#pragma unroll
    for (int i = 0; i < 16; i++) {
        int j = t + (i << 8);
        float v = (j < n) ? p[j] : -INFINITY;
        vals[i] = v;
        mx = fmaxf(mx, v);
    }
#pragma unroll
    for (int o = 16; o; o >>= 1) mx = fmaxf(mx, __shfl_xor_sync(0xffffffffu, mx, o));
    if ((t & 31) == 0) red[t >> 5] = mx;
    __syncthreads();
    if (t < 32) {
        float v = (t < 8) ? red[t] : -INFINITY;
#pragma unroll
        for (int o = 4; o; o >>= 1) v = fmaxf(v, __shfl_xor_sync(0xffffffffu, v, o));
        if (t == 0) red[32] = v;
    }
    __syncthreads();
    mx = red[32];

    float sum = 0.f;
#pragma unroll
    for (int i = 0; i < 16; i++) {
        int j = t + (i << 8);
        float v = (j < n) ? expf(vals[i] - mx) : 0.f;
        vals[i] = v;
        sum += v;
    }
#pragma unroll
    for (int o = 16; o; o >>= 1) sum += __shfl_xor_sync(0xffffffffu, sum, o);
    __syncthreads();
    if ((t & 31) == 0) red[t >> 5] = sum;
    __syncthreads();
    if (t < 32) {
        float v = (t < 8) ? red[t] : 0.f;
#pragma unroll
        for (int o = 4; o; o >>= 1) v += __shfl_xor_sync(0xffffffffu, v, o);
        if (t == 0) red[32] = v;
    }
    __syncthreads();
    const float inv = 1.0f / red[32];
#pragma unroll
    for (int i = 0; i < 16; i++) {
        int j = t + (i << 8);
        p[j] = vals[i] * inv;
    }
}

// ---------------------------------------------------------------------------
// Launch: 3 projection GEMMs -> scores (NT, lower-tri) -> softmax ->
// P@V (NN, k-limited) -> output projection. All on default stream, capturable.
// ---------------------------------------------------------------------------
extern "C" void kernel_launch(void* const* d_in, const int* in_sizes, int n_in,
                              void* d_out, int out_size)
{
    (void)in_sizes; (void)n_in; (void)out_size;

    const float* x  = (const float*)d_in[0];
    const float* Wq = (const float*)d_in[1];
    const float* bq = (const float*)d_in[2];
    const float* Wk = (const float*)d_in[3];
    const float* bk = (const float*)d_in[4];
    const float* Wv = (const float*)d_in[5];
    const float* bv = (const float*)d_in[6];
    const float* Wo = (const float*)d_in[7];
    const float* bo = (const float*)d_in[8];
    float* out = (float*)d_out;

    float *qp, *kp, *vp, *cp, *pp;
    cudaGetSymbolAddress((void**)&qp, g_q);
    cudaGetSymbolAddress((void**)&kp, g_k);
    cudaGetSymbolAddress((void**)&vp, g_v);
    cudaGetSymbolAddress((void**)&cp, g_ctx);
    cudaGetSymbolAddress((void**)&pp, g_p);

    dim3 blk(256);

    // QKV projections: [16384,1024] @ [1024,1024] + bias
    dim3 gproj(DIM / BN, NTOK / BM, 1);
    gemm_nn<<<gproj, blk>>>(x, Wq, bq, qp, NTOK, DIM, DIM, 0, 0, 0, 0);
    gemm_nn<<<gproj, blk>>>(x, Wk, bk, kp, NTOK, DIM, DIM, 0, 0, 0, 0);
    gemm_nn<<<gproj, blk>>>(x, Wv, bv, vp, NTOK, DIM, DIM, 0, 0, 0, 0);

    // Scores: per batch, lower-triangular tiles of Q @ K^T * 1/32
    dim3 gsc(SEQ / BN, SEQ / BM, BATCH);
    gemm_nt_scores<<<gsc, blk>>>(qp, kp, pp, 1.0f / 32.0f);

    // Causal softmax per row
    dim3 gsm(SEQ, BATCH, 1);
    softmax_causal<<<gsm, blk>>>(pp);

    // ctx = P @ V  (k loop limited to the causal extent of each row tile)
    dim3 gpv(DIM / BN, SEQ / BM, BATCH);
    gemm_nn<<<gpv, blk>>>(pp, vp, nullptr, cp, SEQ, DIM, SEQ, 1,
                          (size_t)SEQ * SEQ, (size_t)SEQ * DIM, (size_t)SEQ * DIM);

    // out = ctx @ Wo + bo
    gemm_nn<<<gproj, blk>>>(cp, Wo, bo, out, NTOK, DIM, DIM, 0, 0, 0, 0);
}

// round 4
// speedup vs baseline: 3.0924x; 3.0924x over previous
#include <cuda_runtime.h>
#include <math.h>
#include <stdint.h>

// Problem dims (fixed by the dataset)
#define BATCH 4
#define SEQ   4096
#define DIM   1024
#define NTOK  (BATCH * SEQ)   // 16384

#define KC 32                  // K chunk per smem stage
#define PAD 36                 // row stride in floats (32 + 4 pad)

// flags
#define F_CAUSAL 1   // Kend = min(Kfull, (bm+1)*128)
#define F_TRI    2   // skip tiles with bn > bm
#define F_ROUND  4   // round epilogue output to tf32 (rna)

// Scratch in device globals (no cudaMalloc allowed)
__device__ float g_q[(size_t)NTOK * DIM];
__device__ float g_k[(size_t)NTOK * DIM];
__device__ float g_v[(size_t)NTOK * DIM];
__device__ float g_ctx[(size_t)NTOK * DIM];   // holds rounded x first, then ctx
__device__ float g_p[(size_t)BATCH * SEQ * SEQ];
__device__ float g_wt[(size_t)4 * DIM * DIM];     // Wq^T, Wk^T, Wv^T, Wo^T (tf32-rounded)
__device__ float g_vt[(size_t)BATCH * DIM * SEQ]; // V^T per batch (tf32-rounded)

// ---------------------------------------------------------------------------
// helpers
// ---------------------------------------------------------------------------
__device__ __forceinline__ uint32_t smem_u32(const void* p) {
    uint32_t a;
    asm("{ .reg .u64 t; cvta.to.shared.u64 t, %1; cvt.u32.u64 %0, t; }"
        : "=r"(a) : "l"(p));
    return a;
}

__device__ __forceinline__ float rna_tf32(float x) {
    uint32_t r;
    asm("cvt.rna.tf32.f32 %0, %1;" : "=r"(r) : "f"(x));
    return __uint_as_float(r);
}

__device__ __forceinline__ void cp16(uint32_t saddr, const void* gaddr) {
    asm volatile("cp.async.cg.shared.global [%0], [%1], 16;"
                 :: "r"(saddr), "l"(gaddr));
}
#define CP_COMMIT() asm volatile("cp.async.commit_group;" ::: "memory")
#define CP_WAIT(n)  asm volatile("cp.async.wait_group %0;" :: "n"(n) : "memory")

__device__ __forceinline__ void mma_tf32(float* c, const uint32_t* a, const uint32_t* b) {
    asm volatile(
        "mma.sync.aligned.m16n8k8.row.col.f32.tf32.tf32.f32 "
        "{%0,%1,%2,%3}, {%4,%5,%6,%7}, {%8,%9}, {%0,%1,%2,%3};"
        : "+f"(c[0]), "+f"(c[1]), "+f"(c[2]), "+f"(c[3])
        : "r"(a[0]), "r"(a[1]), "r"(a[2]), "r"(a[3]), "r"(b[0]), "r"(b[1]));
}

// Smem: double buffer, each buf = A[128][PAD] + B[128][PAD] floats
#define BUF_FLOATS (2 * 128 * PAD)           // 9216
#define BUF_BYTES  (BUF_FLOATS * 4)          // 36864
#define B_OFF_B    (128 * PAD * 4)           // 18432 bytes
#define SMEM_SZ    (2 * BUF_BYTES)           // 73728

// ---------------------------------------------------------------------------
// tf32 tensor-core GEMM: C[m,n] = scale * sum_k A[m,k] * Bt[n,k] (+ bias[n])
// A row-major [M x Kfull] (lda), Bt row-major [N x Kfull] (ldb; = B col-major).
// CTA 128x128, 8 warps (4x2), warp tile 32x64, mma m16n8k8.
// Operands must already be tf32-valued fp32 (pre-rounded) for full precision.
// ---------------------------------------------------------------------------
__global__ __launch_bounds__(256, 2) void mma_gemm(
    const float* __restrict__ A, const float* __restrict__ Bt,
    const float* __restrict__ bias, float* __restrict__ C,
    int lda, int ldb, int ldc, int Kfull, int flags, float scale,
    size_t sA, size_t sB, size_t sC)
{
    const int bm = blockIdx.y, bn = blockIdx.x, bz = blockIdx.z;
    if ((flags & F_TRI) && bn > bm) return;

    extern __shared__ __align__(16) float smem[];
    const uint32_t sbase = smem_u32(smem);

    const int tid  = threadIdx.x;
    const int wid  = tid >> 5, lane = tid & 31;
    const int wm   = (wid & 3) * 32;       // warp row offset in tile
    const int wn   = (wid >> 2) * 64;      // warp col offset in tile
    const int gid  = lane >> 2, tig = lane & 3;

    int Kend = Kfull;
    if (flags & F_CAUSAL) { int lim = (bm + 1) * 128; if (lim < Kend) Kend = lim; }
    const int NK = Kend / KC;

    const float* Ab = A + sA * bz + (size_t)(bm * 128) * lda;
    const float* Bb = Bt + sB * bz + (size_t)(bn * 128) * ldb;

    // per-thread gmem->smem mapping: 4 float4 per matrix per chunk
    // idx in [0,1024): r = idx/8 (row 0..127), c = (idx%8)*4 (col 0,4,..28)
    int rr[4], cc[4];
#pragma unroll
    for (int t = 0; t < 4; t++) {
        int idx = tid + t * 256;
        rr[t] = idx >> 3;
        cc[t] = (idx & 7) << 2;
    }

    auto issue = [&](int kc, int buf) {
        const int k0 = kc * KC;
        const uint32_t base = sbase + buf * BUF_BYTES;
#pragma unroll
        for (int t = 0; t < 4; t++) {
            const uint32_t soff = (uint32_t)(rr[t] * PAD + cc[t]) * 4;
            cp16(base + soff, Ab + (size_t)rr[t] * lda + k0 + cc[t]);
            cp16(base + B_OFF_B + soff, Bb + (size_t)rr[t] * ldb + k0 + cc[t]);
        }
        CP_COMMIT();
    };

    float acc[2][8][4];
#pragma unroll
    for (int mt = 0; mt < 2; mt++)
#pragma unroll
        for (int nt = 0; nt < 8; nt++)
#pragma unroll
            for (int j = 0; j < 4; j++) acc[mt][nt][j] = 0.f;

    issue(0, 0);

    for (int kc = 0; kc < NK; kc++) {
        const int cur = kc & 1;
        if (kc + 1 < NK) {
            issue(kc + 1, cur ^ 1);
            CP_WAIT(1);
        } else {
            CP_WAIT(0);
        }
        __syncthreads();

        const float* As = smem + cur * BUF_FLOATS;
        const float* Bs = As + 128 * PAD;

#pragma unroll
        for (int ks = 0; ks < 4; ks++) {
            const int kb = ks * 8 + tig;
            uint32_t a[2][4], b[8][2];
#pragma unroll
            for (int mt = 0; mt < 2; mt++) {
                const int r = wm + mt * 16 + gid;
                a[mt][0] = __float_as_uint(As[r * PAD + kb]);
                a[mt][1] = __float_as_uint(As[(r + 8) * PAD + kb]);
                a[mt][2] = __float_as_uint(As[r * PAD + kb + 4]);
                a[mt][3] = __float_as_uint(As[(r + 8) * PAD + kb + 4]);
            }
#pragma unroll
            for (int nt = 0; nt < 8; nt++) {
                const int col = wn + nt * 8 + gid;
                b[nt][0] = __float_as_uint(Bs[col * PAD + kb]);
                b[nt][1] = __float_as_uint(Bs[col * PAD + kb + 4]);
            }
#pragma unroll
            for (int mt = 0; mt < 2; mt++)
#pragma unroll
                for (int nt = 0; nt < 8; nt++)
                    mma_tf32(acc[mt][nt], a[mt], b[nt]);
        }
        __syncthreads();
    }

    // Epilogue
    const int do_round = flags & F_ROUND;
    float* Cb = C + sC * bz;
#pragma unroll
    for (int mt = 0; mt < 2; mt++) {
        const int row0 = bm * 128 + wm + mt * 16 + gid;
#pragma unroll
        for (int nt = 0; nt < 8; nt++) {
            const int col = bn * 128 + wn + nt * 8 + tig * 2;
            float b0 = 0.f, b1 = 0.f;
            if (bias) { b0 = bias[col]; b1 = bias[col + 1]; }
            float2 v0, v1;
            v0.x = acc[mt][nt][0] * scale + b0;
            v0.y = acc[mt][nt][1] * scale + b1;
            v1.x = acc[mt][nt][2] * scale + b0;
            v1.y = acc[mt][nt][3] * scale + b1;
            if (do_round) {
                v0.x = rna_tf32(v0.x); v0.y = rna_tf32(v0.y);
                v1.x = rna_tf32(v1.x); v1.y = rna_tf32(v1.y);
            }
            *(float2*)(Cb + (size_t)row0 * ldc + col) = v0;
            *(float2*)(Cb + (size_t)(row0 + 8) * ldc + col) = v1;
        }
    }
}

// ---------------------------------------------------------------------------
// Tiled transpose with optional tf32 rounding: out[c, r] = rna(in[r, c]).
// ---------------------------------------------------------------------------
__global__ __launch_bounds__(256) void transpose_k(
    const float* __restrict__ in, float* __restrict__ out,
    int rows, int cols, size_t sIn, size_t sOut)
{
    __shared__ float tile[32][33];
    const int bx = blockIdx.x * 32, by = blockIdx.y * 32, bz = blockIdx.z;
    const float* ip = in + sIn * bz;
    float* op = out + sOut * bz;
    const int tx = threadIdx.x, ty = threadIdx.y;
#pragma unroll
    for (int i = 0; i < 4; i++)
        tile[ty + i * 8][tx] = ip[(size_t)(by + ty + i * 8) * cols + bx + tx];
    __syncthreads();
#pragma unroll
    for (int i = 0; i < 4; i++)
        op[(size_t)(bx + ty + i * 8) * rows + by + tx] = rna_tf32(tile[tx][ty + i * 8]);
}

// ---------------------------------------------------------------------------
// Elementwise tf32 rounding pass (for x).
// ---------------------------------------------------------------------------
__global__ __launch_bounds__(256) void round_pass(
    const float* __restrict__ in, float* __restrict__ out)
{
    const size_t i = ((size_t)blockIdx.x * 256 + threadIdx.x) * 4;
    float4 v = *(const float4*)(in + i);
    v.x = rna_tf32(v.x); v.y = rna_tf32(v.y);
    v.z = rna_tf32(v.z); v.w = rna_tf32(v.w);
    *(float4*)(out + i) = v;
}

// ---------------------------------------------------------------------------
// Causal row softmax; writes full row (zeros beyond diagonal) rounded to tf32.
// ---------------------------------------------------------------------------
__global__ __launch_bounds__(256) void softmax_causal(float* __restrict__ P)
{
    __shared__ float red[33];
    const int row = blockIdx.x;
    const int bz  = blockIdx.y;
    float* p = P + ((size_t)bz * SEQ + row) * SEQ;
    const int n = row + 1;
    const int t = threadIdx.x;

    float vals[16];
    float mx = -INFINITY;
#pragma unroll
    for (int i = 0; i < 16; i++) {
        int j = t + (i << 8);
        float v = (j < n) ? p[j] : -INFINITY;
        vals[i] = v;
        mx = fmaxf(mx, v);
    }
#pragma unroll
    for (int o = 16; o; o >>= 1) mx = fmaxf(mx, __shfl_xor_sync(0xffffffffu, mx, o));
    if ((t & 31) == 0) red[t >> 5] = mx;
    __syncthreads();
    if (t < 32) {
        float v = (t < 8) ? red[t] : -INFINITY;
#pragma unroll
        for (int o = 4; o; o >>= 1) v = fmaxf(v, __shfl_xor_sync(0xffffffffu, v, o));
        if (t == 0) red[32] = v;
    }
    __syncthreads();
    mx = red[32];

    float sum = 0.f;
#pragma unroll
    for (int i = 0; i < 16; i++) {
        int j = t + (i << 8);
        float v = (j < n) ? expf(vals[i] - mx) : 0.f;
        vals[i] = v;
        sum += v;
    }
#pragma unroll
    for (int o = 16; o; o >>= 1) sum += __shfl_xor_sync(0xffffffffu, sum, o);
    __syncthreads();
    if ((t & 31) == 0) red[t >> 5] = sum;
    __syncthreads();
    if (t < 32) {
        float v = (t < 8) ? red[t] : 0.f;
#pragma unroll
        for (int o = 4; o; o >>= 1) v += __shfl_xor_sync(0xffffffffu, v, o);
        if (t == 0) red[32] = v;
    }
    __syncthreads();
    const float inv = 1.0f / red[32];
#pragma unroll
    for (int i = 0; i < 16; i++) {
        int j = t + (i << 8);
        p[j] = rna_tf32(vals[i] * inv);
    }
}

// ---------------------------------------------------------------------------
// Launch
// ---------------------------------------------------------------------------
extern "C" void kernel_launch(void* const* d_in, const int* in_sizes, int n_in,
                              void* d_out, int out_size)
{
    (void)in_sizes; (void)n_in; (void)out_size;

    const float* x  = (const float*)d_in[0];
    const float* Wq = (const float*)d_in[1];
    const float* bq = (const float*)d_in[2];
    const float* Wk = (const float*)d_in[3];
    const float* bk = (const float*)d_in[4];
    const float* Wv = (const float*)d_in[5];
    const float* bv = (const float*)d_in[6];
    const float* Wo = (const float*)d_in[7];
    const float* bo = (const float*)d_in[8];
    float* out = (float*)d_out;

    float *qp, *kp, *vp, *cp, *pp, *wt, *vt;
    cudaGetSymbolAddress((void**)&qp, g_q);
    cudaGetSymbolAddress((void**)&kp, g_k);
    cudaGetSymbolAddress((void**)&vp, g_v);
    cudaGetSymbolAddress((void**)&cp, g_ctx);
    cudaGetSymbolAddress((void**)&pp, g_p);
    cudaGetSymbolAddress((void**)&wt, g_wt);
    cudaGetSymbolAddress((void**)&vt, g_vt);

    cudaFuncSetAttribute(mma_gemm, cudaFuncAttributeMaxDynamicSharedMemorySize, SMEM_SZ);

    float* wqt = wt;
    float* wkt = wt + (size_t)DIM * DIM;
    float* wvt = wt + (size_t)2 * DIM * DIM;
    float* wot = wt + (size_t)3 * DIM * DIM;

    dim3 tb(32, 8);
    dim3 tgw(DIM / 32, DIM / 32, 1);
    transpose_k<<<tgw, tb>>>(Wq, wqt, DIM, DIM, 0, 0);
    transpose_k<<<tgw, tb>>>(Wk, wkt, DIM, DIM, 0, 0);
    transpose_k<<<tgw, tb>>>(Wv, wvt, DIM, DIM, 0, 0);
    transpose_k<<<tgw, tb>>>(Wo, wot, DIM, DIM, 0, 0);

    // round x -> cp (g_ctx doubles as rounded-x until the P@V stage)
    round_pass<<<(unsigned)((size_t)NTOK * DIM / 4 / 256), 256>>>(x, cp);

    dim3 blk(256);

    // QKV projections: [16384,1024] @ Wt^T + bias ; Q,K,ctx rounded for reuse as A
    dim3 gproj(DIM / 128, NTOK / 128, 1);
    mma_gemm<<<gproj, blk, SMEM_SZ>>>(cp, wqt, bq, qp, DIM, DIM, DIM, DIM, F_ROUND, 1.0f, 0, 0, 0);
    mma_gemm<<<gproj, blk, SMEM_SZ>>>(cp, wkt, bk, kp, DIM, DIM, DIM, DIM, F_ROUND, 1.0f, 0, 0, 0);
    mma_gemm<<<gproj, blk, SMEM_SZ>>>(cp, wvt, bv, vp, DIM, DIM, DIM, DIM, 0, 1.0f, 0, 0, 0);

    // Scores: P = (Q @ K^T) / 32, lower-triangular tiles only
    dim3 gsc(SEQ / 128, SEQ / 128, BATCH);
    mma_gemm<<<gsc, blk, SMEM_SZ>>>(qp, kp, nullptr, pp, DIM, DIM, SEQ, DIM, F_TRI,
                                    1.0f / 32.0f,
                                    (size_t)SEQ * DIM, (size_t)SEQ * DIM, (size_t)SEQ * SEQ);

    // Causal softmax per row (rounds P to tf32)
    dim3 gsm(SEQ, BATCH, 1);
    softmax_causal<<<gsm, 256>>>(pp);

    // Transpose V per batch: [SEQ, DIM] -> [DIM, SEQ], rounded
    dim3 tgv(DIM / 32, SEQ / 32, BATCH);
    transpose_k<<<tgv, tb>>>(vp, vt, SEQ, DIM, (size_t)SEQ * DIM, (size_t)DIM * SEQ);

    // ctx = P @ V (K loop causally limited); rounded since it feeds final GEMM
    dim3 gpv(DIM / 128, SEQ / 128, BATCH);
    mma_gemm<<<gpv, blk, SMEM_SZ>>>(pp, vt, nullptr, cp, SEQ, SEQ, DIM, SEQ,
                                    F_CAUSAL | F_ROUND, 1.0f,
                                    (size_t)SEQ * SEQ, (size_t)DIM * SEQ, (size_t)SEQ * DIM);

    // out = ctx @ Wo^T + bo  (no rounding on final output)
    mma_gemm<<<gproj, blk, SMEM_SZ>>>(cp, wot, bo, out, DIM, DIM, DIM, DIM, 0, 1.0f, 0, 0, 0);
}